// round 1
// baseline (speedup 1.0000x reference)
#include <cuda_runtime.h>

#define D        64
#define EXPERTS  8
#define RANGE    2048
#define BLOCK    256

// packed fp32x2 FMA: d = a*b + d  (SASS FFMA2, sm_103a)
__device__ __forceinline__ void ffma2(unsigned long long& d,
                                      unsigned long long a,
                                      unsigned long long b) {
    asm("fma.rn.f32x2 %0, %1, %2, %0;" : "+l"(d) : "l"(a), "l"(b));
}

__device__ __forceinline__ unsigned long long packf2(float x) {
    unsigned long long r;
    asm("mov.b64 %0, {%1, %1};" : "=l"(r) : "f"(x));
    return r;
}

__global__ __launch_bounds__(BLOCK)
void moe_split_kernel(const float* __restrict__ features,
                      const int*   __restrict__ inds,
                      const float* __restrict__ W,
                      const float* __restrict__ b,
                      float*       __restrict__ out,
                      int N)
{
    __shared__ __align__(16) float sW[D * D];   // W[e] : [k][j]
    __shared__ __align__(16) float sB[D];
    __shared__ int sQ[RANGE];
    __shared__ int sCnt;

    const int e     = blockIdx.y;
    const int start = blockIdx.x * RANGE;
    const int end   = min(N, start + RANGE);
    const int tid   = threadIdx.x;
    const int lane  = tid & 31;
    const int wid   = tid >> 5;

    if (tid == 0) sCnt = 0;

    // ---- load expert weight + bias into shared (coalesced float4) ----
    {
        const float4* Wg  = (const float4*)(W + (size_t)e * D * D);
        float4*       sW4 = (float4*)sW;
        #pragma unroll
        for (int i = tid; i < D * D / 4; i += BLOCK) sW4[i] = Wg[i];
        if (tid < D) sB[tid] = b[e * D + tid];
    }
    __syncthreads();

    // ---- phase A: ballot-compact tokens of this expert into shared queue ----
    for (int g0 = start; g0 < end; g0 += BLOCK) {
        int  g = g0 + tid;
        bool m = (g < end) && (inds[g] == e);
        unsigned bal = __ballot_sync(0xffffffffu, m);
        int cnt = __popc(bal);
        int base;
        if (lane == 0) base = atomicAdd(&sCnt, cnt);
        base = __shfl_sync(0xffffffffu, base, 0);
        if (m) sQ[base + __popc(bal & ((1u << lane) - 1u))] = g;
    }
    __syncthreads();
    const int M = sCnt;

    // ---- phase B: each warp takes 32 same-expert tokens; lane = token ----
    for (int base = wid * 32; base < M; base += (BLOCK / 32) * 32) {
        int  idx   = base + lane;
        bool valid = (idx < M);
        int  token = sQ[valid ? idx : 0];   // M>=1 here since loop entered

        const float4* frow = (const float4*)(features + (size_t)token * D);

        // 64 fp32 accumulators as 32 packed f32x2 pairs, init with bias
        unsigned long long acc[D / 2];
        const unsigned long long* bp = (const unsigned long long*)sB;
        #pragma unroll
        for (int j = 0; j < D / 2; ++j) acc[j] = bp[j];

        #pragma unroll 1
        for (int kk = 0; kk < 4; ++kk) {
            float4 f[4];
            #pragma unroll
            for (int i = 0; i < 4; ++i) f[i] = frow[kk * 4 + i];
            const float* fs = (const float*)f;

            #pragma unroll
            for (int i = 0; i < 16; ++i) {
                unsigned long long fk2 = packf2(fs[i]);
                // all lanes read the same row -> LDS broadcast, conflict-free
                const unsigned long long* wr =
                    (const unsigned long long*)(sW + (kk * 16 + i) * D);
                #pragma unroll
                for (int j = 0; j < D / 2; ++j) ffma2(acc[j], fk2, wr[j]);
            }
        }

        if (valid) {
            float4* orow = (float4*)(out + (size_t)token * D);
            #pragma unroll
            for (int q = 0; q < D / 4; ++q) {
                float2 lo = *(float2*)&acc[2 * q];
                float2 hi = *(float2*)&acc[2 * q + 1];
                orow[q] = make_float4(lo.x, lo.y, hi.x, hi.y);
            }
        }
    }
}

extern "C" void kernel_launch(void* const* d_in, const int* in_sizes, int n_in,
                              void* d_out, int out_size) {
    const float* features = (const float*)d_in[0];
    const int*   inds     = (const int*)d_in[1];
    const float* W        = (const float*)d_in[2];
    const float* b        = (const float*)d_in[3];
    float*       out      = (float*)d_out;

    int N = in_sizes[0] / D;
    dim3 grid((N + RANGE - 1) / RANGE, EXPERTS);
    moe_split_kernel<<<grid, BLOCK>>>(features, inds, W, b, out, N);
}

// round 4
// speedup vs baseline: 1.1283x; 1.1283x over previous
#include <cuda_runtime.h>

#define D       64
#define EXPERTS 8
#define RANGE   2048
#define TILE    128
#define BLOCK   256
#define PITCH   132   // 128 tokens + 4 floats pad (keeps 16B alignment, breaks stride-128 conflicts)

// packed fp32x2 FMA: d = a*b + d  (SASS FFMA2, sm_103a)
__device__ __forceinline__ void ffma2(unsigned long long& d,
                                      unsigned long long a,
                                      unsigned long long b) {
    asm("fma.rn.f32x2 %0, %1, %2, %0;" : "+l"(d) : "l"(a), "l"(b));
}
__device__ __forceinline__ unsigned long long packf2(float x) {
    unsigned long long r;
    asm("mov.b64 %0, {%1, %1};" : "=l"(r) : "f"(x));
    return r;
}
__device__ __forceinline__ unsigned long long pack2(float lo, float hi) {
    unsigned long long r;
    asm("mov.b64 %0, {%1, %2};" : "=l"(r) : "f"(lo), "f"(hi));
    return r;
}
__device__ __forceinline__ float2 unpack2(unsigned long long v) {
    float2 f;
    asm("mov.b64 {%0, %1}, %2;" : "=f"(f.x), "=f"(f.y) : "l"(v));
    return f;
}

// dynamic smem layout (floats):
//   sW   [0, 4096)              expert weight, row-major [k][j]
//   sB   [4096, 4160)           bias
//   sF   [4160, 4160+64*PITCH)  transposed feature tile [k][t]
//   sQ   int[RANGE]             token queue
//   sCnt int
#define SMEM_FLOATS (D*D + D + D*PITCH)
#define SMEM_BYTES  (SMEM_FLOATS*4 + RANGE*4 + 16)

extern __shared__ float smem[];

__global__ __launch_bounds__(BLOCK, 2)
void moe_split_kernel(const float* __restrict__ features,
                      const int*   __restrict__ inds,
                      const float* __restrict__ W,
                      const float* __restrict__ b,
                      float*       __restrict__ out,
                      int N)
{
    float* sW   = smem;
    float* sB   = smem + D * D;
    float* sF   = sB + D;
    int*   sQ   = (int*)(sF + D * PITCH);
    int*   sCnt = sQ + RANGE;

    const int e     = blockIdx.y;
    const int start = blockIdx.x * RANGE;
    const int end   = min(N, start + RANGE);
    const int tid   = threadIdx.x;
    const int lane  = tid & 31;
    const int wid   = tid >> 5;

    if (tid == 0) *sCnt = 0;

    // ---- load expert weight + bias (coalesced float4) ----
    {
        const float4* Wg  = (const float4*)(W + (size_t)e * D * D);
        float4*       sW4 = (float4*)sW;
        #pragma unroll
        for (int i = tid; i < D * D / 4; i += BLOCK) sW4[i] = Wg[i];
        if (tid < D) sB[tid] = b[e * D + tid];
    }
    __syncthreads();

    // ---- phase A: ballot-compact this expert's tokens into queue ----
    for (int g0 = start; g0 < end; g0 += BLOCK) {
        int  g = g0 + tid;
        bool m = (g < end) && (inds[g] == e);
        unsigned bal = __ballot_sync(0xffffffffu, m);
        int base;
        if (lane == 0) base = atomicAdd(sCnt, __popc(bal));
        base = __shfl_sync(0xffffffffu, base, 0);
        if (m) sQ[base + __popc(bal & ((1u << lane) - 1u))] = g;
    }
    __syncthreads();
    const int M = *sCnt;

    // ---- phase B: process tiles of 128 tokens ----
    for (int tb = 0; tb < M; tb += TILE) {
        const int Mt = min(TILE, M - tb);

        __syncthreads();   // WAR: previous compute done reading sF

        // stage features transposed: warp w fills cols i = w*16 .. w*16+15
        #pragma unroll
        for (int r = 0; r < TILE / 8; ++r) {
            int i     = wid * (TILE / 8) + r;
            int qi    = (i < Mt) ? i : 0;
            int token = sQ[tb + qi];
            float2 v  = *(const float2*)(features + (size_t)token * D + 2 * lane);
            sF[(2 * lane)     * PITCH + i] = v.x;
            sF[(2 * lane + 1) * PITCH + i] = v.y;
        }
        __syncthreads();

        // compute: warp = 8 output cols (j0), lane = 4 consecutive tokens (t0)
        const int j0 = wid * 8;
        const int t0 = lane * 4;

        unsigned long long acc[4][4];
        {
            const unsigned long long* bp = (const unsigned long long*)(sB + j0);
            #pragma unroll
            for (int t = 0; t < 4; ++t)
                #pragma unroll
                for (int p = 0; p < 4; ++p) acc[t][p] = bp[p];
        }

        const float* fptr = sF + t0;
        const float* wptr = sW + j0;

        #pragma unroll 8
        for (int k = 0; k < D; ++k) {
            float4 f  = *(const float4*)(fptr + k * PITCH);      // 4 tokens, conflict-free
            float4 wA = *(const float4*)(wptr + k * D);          // broadcast
            float4 wB = *(const float4*)(wptr + k * D + 4);      // broadcast

            unsigned long long wp0 = pack2(wA.x, wA.y);
            unsigned long long wp1 = pack2(wA.z, wA.w);
            unsigned long long wp2 = pack2(wB.x, wB.y);
            unsigned long long wp3 = pack2(wB.z, wB.w);

            unsigned long long fk0 = packf2(f.x);
            unsigned long long fk1 = packf2(f.y);
            unsigned long long fk2 = packf2(f.z);
            unsigned long long fk3 = packf2(f.w);

            ffma2(acc[0][0], fk0, wp0); ffma2(acc[0][1], fk0, wp1);
            ffma2(acc[0][2], fk0, wp2); ffma2(acc[0][3], fk0, wp3);
            ffma2(acc[1][0], fk1, wp0); ffma2(acc[1][1], fk1, wp1);
            ffma2(acc[1][2], fk1, wp2); ffma2(acc[1][3], fk1, wp3);
            ffma2(acc[2][0], fk2, wp0); ffma2(acc[2][1], fk2, wp1);
            ffma2(acc[2][2], fk2, wp2); ffma2(acc[2][3], fk2, wp3);
            ffma2(acc[3][0], fk3, wp0); ffma2(acc[3][1], fk3, wp1);
            ffma2(acc[3][2], fk3, wp2); ffma2(acc[3][3], fk3, wp3);
        }

        // store: 2 x STG.128 per valid token
        #pragma unroll
        for (int t = 0; t < 4; ++t) {
            int i = t0 + t;
            if (i < Mt) {
                int token = sQ[tb + i];
                float2 a0 = unpack2(acc[t][0]), a1 = unpack2(acc[t][1]);
                float2 a2 = unpack2(acc[t][2]), a3 = unpack2(acc[t][3]);
                float4* orow = (float4*)(out + (size_t)token * D + j0);
                orow[0] = make_float4(a0.x, a0.y, a1.x, a1.y);
                orow[1] = make_float4(a2.x, a2.y, a3.x, a3.y);
            }
        }
    }
}

extern "C" void kernel_launch(void* const* d_in, const int* in_sizes, int n_in,
                              void* d_out, int out_size) {
    const float* features = (const float*)d_in[0];
    const int*   inds     = (const int*)d_in[1];
    const float* W        = (const float*)d_in[2];
    const float* b        = (const float*)d_in[3];
    float*       out      = (float*)d_out;

    int N = in_sizes[0] / D;

    (void)cudaFuncSetAttribute(moe_split_kernel,
                               cudaFuncAttributeMaxDynamicSharedMemorySize,
                               SMEM_BYTES);

    dim3 grid((N + RANGE - 1) / RANGE, EXPERTS);
    moe_split_kernel<<<grid, BLOCK, SMEM_BYTES>>>(features, inds, W, b, out, N);
}

// round 5
// speedup vs baseline: 1.5390x; 1.3640x over previous
#include <cuda_runtime.h>

#define D        64
#define EXPERTS  8
#define NTOK     (1 << 20)
#define SCAN_TPB 256
#define SCAN_TOKENS 4096
#define NUM_SCAN_CTAS (NTOK / SCAN_TOKENS)   // 256
#define GBLOCK   256
#define TILE     128

// ---------------- device scratch (no allocation allowed) ----------------
__device__ int g_perm[NTOK];
__device__ int g_blockCnt[NUM_SCAN_CTAS * EXPERTS];
__device__ int g_blockBase[NUM_SCAN_CTAS * EXPERTS];
__device__ int g_cnt[EXPERTS];
__device__ int g_off[EXPERTS + 1];
__device__ int g_tileOfs[EXPERTS + 1];

// ---------------- fp32x2 helpers (SASS FFMA2 on sm_103a) ----------------
__device__ __forceinline__ void ffma2(unsigned long long& d,
                                      unsigned long long a,
                                      unsigned long long b) {
    asm("fma.rn.f32x2 %0, %1, %2, %0;" : "+l"(d) : "l"(a), "l"(b));
}
__device__ __forceinline__ unsigned long long packf2(float x) {
    unsigned long long r;
    asm("mov.b64 %0, {%1, %1};" : "=l"(r) : "f"(x));
    return r;
}
__device__ __forceinline__ unsigned long long pack2(float lo, float hi) {
    unsigned long long r;
    asm("mov.b64 %0, {%1, %2};" : "=l"(r) : "f"(lo), "f"(hi));
    return r;
}
__device__ __forceinline__ float2 unpack2(unsigned long long v) {
    float2 f;
    asm("mov.b64 {%0, %1}, %2;" : "=f"(f.x), "=f"(f.y) : "l"(v));
    return f;
}

// ---------------- kernel A: per-CTA histogram ----------------
__global__ __launch_bounds__(SCAN_TPB)
void count_kernel(const int* __restrict__ inds, int N) {
    const int cta = blockIdx.x, tid = threadIdx.x;
    const int base = cta * SCAN_TOKENS;
    int c[EXPERTS];
    #pragma unroll
    for (int q = 0; q < EXPERTS; ++q) c[q] = 0;

    for (int i = tid; i < SCAN_TOKENS; i += SCAN_TPB) {
        int g = base + i;
        if (g < N) {
            int e = inds[g];
            #pragma unroll
            for (int q = 0; q < EXPERTS; ++q) c[q] += (e == q);
        }
    }
    #pragma unroll
    for (int q = 0; q < EXPERTS; ++q)
        c[q] = __reduce_add_sync(0xffffffffu, c[q]);

    __shared__ int w[SCAN_TPB / 32][EXPERTS];
    if ((tid & 31) == 0) {
        #pragma unroll
        for (int q = 0; q < EXPERTS; ++q) w[tid >> 5][q] = c[q];
    }
    __syncthreads();
    if (tid < EXPERTS) {
        int s = 0;
        #pragma unroll
        for (int ww = 0; ww < SCAN_TPB / 32; ++ww) s += w[ww][tid];
        g_blockCnt[cta * EXPERTS + tid] = s;
    }
}

// ---------------- kernel B: scan (1 CTA) ----------------
__global__ __launch_bounds__(NUM_SCAN_CTAS)
void scan_kernel() {
    __shared__ int s[NUM_SCAN_CTAS];
    __shared__ int sTot[EXPERTS];
    const int tid = threadIdx.x;

    for (int e = 0; e < EXPERTS; ++e) {
        int v = g_blockCnt[tid * EXPERTS + e];
        s[tid] = v;
        __syncthreads();
        for (int ofs = 1; ofs < NUM_SCAN_CTAS; ofs <<= 1) {
            int t = (tid >= ofs) ? s[tid - ofs] : 0;
            __syncthreads();
            s[tid] += t;
            __syncthreads();
        }
        if (tid == NUM_SCAN_CTAS - 1) sTot[e] = s[tid];
        g_blockBase[tid * EXPERTS + e] = s[tid] - v;   // exclusive (intra), off added later
        __syncthreads();
    }
    if (tid == 0) {
        int off = 0, tofs = 0;
        for (int e = 0; e < EXPERTS; ++e) {
            g_cnt[e] = sTot[e];
            g_off[e] = off;
            g_tileOfs[e] = tofs;
            off  += sTot[e];
            tofs += (sTot[e] + TILE - 1) / TILE;
        }
        g_off[EXPERTS] = off;
        g_tileOfs[EXPERTS] = tofs;
    }
    __syncthreads();
    #pragma unroll
    for (int e = 0; e < EXPERTS; ++e)
        g_blockBase[tid * EXPERTS + e] += g_off[e];
}

// ---------------- kernel C: scatter token ids ----------------
__global__ __launch_bounds__(SCAN_TPB)
void scatter_kernel(const int* __restrict__ inds, int N) {
    __shared__ int ctr[EXPERTS];
    const int cta = blockIdx.x, tid = threadIdx.x;
    if (tid < EXPERTS) ctr[tid] = g_blockBase[cta * EXPERTS + tid];
    __syncthreads();
    const int base = cta * SCAN_TOKENS;
    for (int i = tid; i < SCAN_TOKENS; i += SCAN_TPB) {
        int g = base + i;
        if (g < N) {
            int e = inds[g];
            int slot = atomicAdd(&ctr[e], 1);
            g_perm[slot] = g;
        }
    }
}

// ---------------- kernel D: balanced per-expert GEMM ----------------
// dynamic smem layout (floats):
//   sW [0,4096)  weight [k][j]
//   sB [4096,4160)
//   sF [4160,4160+8192)  swizzled transposed features:
//       element (k,t): g=t>>2, r=t&3, g' = g ^ ((k>>1)&7), addr = k*128 + g'*4 + r
//   sT int[128]  token ids
#define GSMEM_FLOATS (D*D + D + D*TILE)
#define GSMEM_BYTES  (GSMEM_FLOATS*4 + TILE*4)

extern __shared__ float gsm[];

__global__ __launch_bounds__(GBLOCK, 2)
void gemm_kernel(const float* __restrict__ features,
                 const float* __restrict__ W,
                 const float* __restrict__ b,
                 float* __restrict__ out)
{
    float* sW = gsm;
    float* sB = gsm + D * D;
    float* sF = sB + D;
    int*   sT = (int*)(sF + D * TILE);

    const int t = blockIdx.x;
    if (t >= g_tileOfs[EXPERTS]) return;

    int e = 0;
    #pragma unroll
    for (int q = 1; q < EXPERTS; ++q) if (t >= g_tileOfs[q]) e = q;
    const int tIdx     = t - g_tileOfs[e];
    const int rowStart = g_off[e] + tIdx * TILE;
    const int Mt       = min(TILE, g_cnt[e] - tIdx * TILE);

    const int tid  = threadIdx.x;
    const int lane = tid & 31;
    const int wid  = tid >> 5;

    // token list (pad with first token; padded outputs never stored)
    if (tid < TILE)
        sT[tid] = g_perm[rowStart + (tid < Mt ? tid : 0)];

    // expert weights + bias
    {
        const float4* Wg  = (const float4*)(W + (size_t)e * D * D);
        float4*       sW4 = (float4*)sW;
        #pragma unroll
        for (int i = tid; i < D * D / 4; i += GBLOCK) sW4[i] = Wg[i];
        if (tid < D) sB[tid] = b[e * D + tid];
    }
    __syncthreads();   // sT ready

    // stage features, swizzled transpose (2-way STS conflicts max)
    {
        const int i2 = lane >> 4, c = lane & 15;
        const int s  = c & 7;                 // (k>>1)&7 is c&7 for all four k below
        #pragma unroll
        for (int it = 0; it < 8; ++it) {
            int i     = wid * 16 + it * 2 + i2;
            int token = sT[i];
            const float2* fr = (const float2*)(features + (size_t)token * D);
            float2 vA = fr[c];        // k = 2c, 2c+1
            float2 vB = fr[16 + c];   // k = 32+2c, 33+2c
            int g  = i >> 2, r = i & 3;
            int gp = (g ^ s) * 4 + r;
            sF[(2*c)      * TILE + gp] = vA.x;
            sF[(2*c + 1)  * TILE + gp] = vA.y;
            sF[(32 + 2*c) * TILE + gp] = vB.x;
            sF[(33 + 2*c) * TILE + gp] = vB.y;
        }
    }
    __syncthreads();

    // compute: warp = 8 output cols (j0), lane = tokens 4*lane..4*lane+3
    const int j0 = wid * 8;

    unsigned long long acc[4][4];
    {
        const unsigned long long* bp = (const unsigned long long*)(sB + j0);
        #pragma unroll
        for (int tt = 0; tt < 4; ++tt)
            #pragma unroll
            for (int p = 0; p < 4; ++p) acc[tt][p] = bp[p];
    }

    const float4* sF4  = (const float4*)sF;
    const float*  wptr = sW + j0;

    #pragma unroll 8
    for (int k = 0; k < D; ++k) {
        int   s  = (k >> 1) & 7;
        float4 f  = sF4[k * (TILE/4) + (lane ^ s)];      // conflict-free
        float4 wA = *(const float4*)(wptr + k * D);      // broadcast
        float4 wB = *(const float4*)(wptr + k * D + 4);  // broadcast

        unsigned long long wp0 = pack2(wA.x, wA.y);
        unsigned long long wp1 = pack2(wA.z, wA.w);
        unsigned long long wp2 = pack2(wB.x, wB.y);
        unsigned long long wp3 = pack2(wB.z, wB.w);

        unsigned long long fk0 = packf2(f.x);
        unsigned long long fk1 = packf2(f.y);
        unsigned long long fk2 = packf2(f.z);
        unsigned long long fk3 = packf2(f.w);

        ffma2(acc[0][0], fk0, wp0); ffma2(acc[0][1], fk0, wp1);
        ffma2(acc[0][2], fk0, wp2); ffma2(acc[0][3], fk0, wp3);
        ffma2(acc[1][0], fk1, wp0); ffma2(acc[1][1], fk1, wp1);
        ffma2(acc[1][2], fk1, wp2); ffma2(acc[1][3], fk1, wp3);
        ffma2(acc[2][0], fk2, wp0); ffma2(acc[2][1], fk2, wp1);
        ffma2(acc[2][2], fk2, wp2); ffma2(acc[2][3], fk2, wp3);
        ffma2(acc[3][0], fk3, wp0); ffma2(acc[3][1], fk3, wp1);
        ffma2(acc[3][2], fk3, wp2); ffma2(acc[3][3], fk3, wp3);
    }

    // store (each warp writes its 32-B slice of each token row = full sectors)
    const int t0 = lane * 4;
    #pragma unroll
    for (int tt = 0; tt < 4; ++tt) {
        int i = t0 + tt;
        if (i < Mt) {
            int token = sT[i];
            float2 a0 = unpack2(acc[tt][0]), a1 = unpack2(acc[tt][1]);
            float2 a2 = unpack2(acc[tt][2]), a3 = unpack2(acc[tt][3]);
            float4* orow = (float4*)(out + (size_t)token * D + j0);
            orow[0] = make_float4(a0.x, a0.y, a1.x, a1.y);
            orow[1] = make_float4(a2.x, a2.y, a3.x, a3.y);
        }
    }
}

// ---------------- launch ----------------
extern "C" void kernel_launch(void* const* d_in, const int* in_sizes, int n_in,
                              void* d_out, int out_size) {
    const float* features = (const float*)d_in[0];
    const int*   inds     = (const int*)d_in[1];
    const float* W        = (const float*)d_in[2];
    const float* b        = (const float*)d_in[3];
    float*       out      = (float*)d_out;

    int N = in_sizes[0] / D;

    (void)cudaFuncSetAttribute(gemm_kernel,
                               cudaFuncAttributeMaxDynamicSharedMemorySize,
                               GSMEM_BYTES);

    int nScan = (N + SCAN_TOKENS - 1) / SCAN_TOKENS;     // 256 for N=1M
    count_kernel<<<nScan, SCAN_TPB>>>(inds, N);
    scan_kernel<<<1, NUM_SCAN_CTAS>>>();
    scatter_kernel<<<nScan, SCAN_TPB>>>(inds, N);

    int maxTiles = (N + TILE - 1) / TILE + EXPERTS;      // upper bound; excess CTAs exit
    gemm_kernel<<<maxTiles, GBLOCK, GSMEM_BYTES>>>(features, W, b, out);
}

// round 7
// speedup vs baseline: 1.8848x; 1.2247x over previous
#include <cuda_runtime.h>

#define D        64
#define EXPERTS  8
#define NTOK     (1 << 20)
#define SCAN_TPB 256
#define SCAN_TOKENS 4096
#define NUM_SCAN_CTAS (NTOK / SCAN_TOKENS)   // 256
#define GBLOCK   256
#define TILE     128
#define NCTA_GEMM 296    // 2 CTAs per SM x 148 SMs, persistent
#define KSPLIT   16

typedef unsigned long long ull;

// ---------------- device scratch ----------------
__device__ int g_perm[NTOK];
__device__ int g_blockCnt[NUM_SCAN_CTAS * EXPERTS];
__device__ int g_blockBase[NUM_SCAN_CTAS * EXPERTS];
__device__ int g_cnt[EXPERTS];
__device__ int g_off[EXPERTS + 1];
__device__ int g_tileOfs[EXPERTS + 1];

// ---------------- fp32x2 helpers (SASS FFMA2 on sm_103a) ----------------
__device__ __forceinline__ void ffma2(ull& d, ull a, ull b) {
    asm("fma.rn.f32x2 %0, %1, %2, %0;" : "+l"(d) : "l"(a), "l"(b));
}
__device__ __forceinline__ ull packf2(float x) {
    ull r; asm("mov.b64 %0, {%1, %1};" : "=l"(r) : "f"(x)); return r;
}
__device__ __forceinline__ float2 unpack2(ull v) {
    float2 f; asm("mov.b64 {%0, %1}, %2;" : "=f"(f.x), "=f"(f.y) : "l"(v)); return f;
}

// ---------------- kernel A: per-CTA histogram ----------------
__global__ __launch_bounds__(SCAN_TPB)
void count_kernel(const int* __restrict__ inds, int N) {
    const int cta = blockIdx.x, tid = threadIdx.x;
    const int base = cta * SCAN_TOKENS;
    int c[EXPERTS];
    #pragma unroll
    for (int q = 0; q < EXPERTS; ++q) c[q] = 0;
    for (int i = tid; i < SCAN_TOKENS; i += SCAN_TPB) {
        int g = base + i;
        if (g < N) {
            int e = inds[g];
            #pragma unroll
            for (int q = 0; q < EXPERTS; ++q) c[q] += (e == q);
        }
    }
    #pragma unroll
    for (int q = 0; q < EXPERTS; ++q)
        c[q] = __reduce_add_sync(0xffffffffu, c[q]);
    __shared__ int w[SCAN_TPB / 32][EXPERTS];
    if ((tid & 31) == 0) {
        #pragma unroll
        for (int q = 0; q < EXPERTS; ++q) w[tid >> 5][q] = c[q];
    }
    __syncthreads();
    if (tid < EXPERTS) {
        int s = 0;
        #pragma unroll
        for (int ww = 0; ww < SCAN_TPB / 32; ++ww) s += w[ww][tid];
        g_blockCnt[cta * EXPERTS + tid] = s;
    }
}

// ---------------- kernel B: scan (1 CTA) ----------------
__global__ __launch_bounds__(NUM_SCAN_CTAS)
void scan_kernel() {
    __shared__ int s[NUM_SCAN_CTAS];
    __shared__ int sTot[EXPERTS];
    const int tid = threadIdx.x;
    for (int e = 0; e < EXPERTS; ++e) {
        int v = g_blockCnt[tid * EXPERTS + e];
        s[tid] = v;
        __syncthreads();
        for (int ofs = 1; ofs < NUM_SCAN_CTAS; ofs <<= 1) {
            int t = (tid >= ofs) ? s[tid - ofs] : 0;
            __syncthreads();
            s[tid] += t;
            __syncthreads();
        }
        if (tid == NUM_SCAN_CTAS - 1) sTot[e] = s[tid];
        g_blockBase[tid * EXPERTS + e] = s[tid] - v;
        __syncthreads();
    }
    if (tid == 0) {
        int off = 0, tofs = 0;
        for (int e = 0; e < EXPERTS; ++e) {
            g_cnt[e] = sTot[e];
            g_off[e] = off;
            g_tileOfs[e] = tofs;
            off  += sTot[e];
            tofs += (sTot[e] + TILE - 1) / TILE;
        }
        g_off[EXPERTS] = off;
        g_tileOfs[EXPERTS] = tofs;
    }
    __syncthreads();
    #pragma unroll
    for (int e = 0; e < EXPERTS; ++e)
        g_blockBase[tid * EXPERTS + e] += g_off[e];
}

// ---------------- kernel C: scatter token ids ----------------
__global__ __launch_bounds__(SCAN_TPB)
void scatter_kernel(const int* __restrict__ inds, int N) {
    __shared__ int ctr[EXPERTS];
    const int cta = blockIdx.x, tid = threadIdx.x;
    if (tid < EXPERTS) ctr[tid] = g_blockBase[cta * EXPERTS + tid];
    __syncthreads();
    const int base = cta * SCAN_TOKENS;
    for (int i = tid; i < SCAN_TOKENS; i += SCAN_TPB) {
        int g = base + i;
        if (g < N) {
            int e = inds[g];
            int slot = atomicAdd(&ctr[e], 1);
            g_perm[slot] = g;
        }
    }
}

// ---------------- kernel D: persistent pipelined GEMM ----------------
// smem floats: sW 4096 | sB 64 | sF0 8192 | sF1 8192  then ints: sT0 128 | sT1 128 | sMeta 25
#define GSMEM_BYTES ((D*D + D + 2*D*TILE)*4 + (2*TILE + 32)*4)

extern __shared__ float gsm[];

__global__ __launch_bounds__(GBLOCK, 2)
void gemm_kernel(const float* __restrict__ features,
                 const float* __restrict__ W,
                 const float* __restrict__ b,
                 float* __restrict__ out)
{
    float* sW  = gsm;
    float* sB  = gsm + D * D;
    float* sF0 = sB + D;
    float* sF1 = sF0 + D * TILE;
    int*   sT0 = (int*)(sF1 + D * TILE);
    int*   sT1 = sT0 + TILE;
    int*   sMeta = sT1 + TILE;   // [0..8]=tileOfs, [9..16]=off, [17..24]=cnt

    const int tid  = threadIdx.x;
    const int lane = tid & 31;
    const int wid  = tid >> 5;

    if (tid < 9)            sMeta[tid] = g_tileOfs[tid];
    else if (tid < 17)      sMeta[tid] = g_off[tid - 9];
    else if (tid < 25)      sMeta[tid] = g_cnt[tid - 17];
    __syncthreads();

    const int totalTiles = sMeta[8];
    const int chunk = (totalTiles + gridDim.x - 1) / gridDim.x;
    const int t0 = blockIdx.x * chunk;
    const int t1 = min(totalTiles, t0 + chunk);
    if (t0 >= t1) return;

    // gather geometry (fixed per thread)
    const int i2 = lane >> 4;
    const int c  = lane & 15;
    const int sw = c & 7;

    // ---- tile info helper ----
    auto tileInfo = [&](int t, int& e, int& rowStart, int& Mt) {
        e = 0;
        #pragma unroll
        for (int q = 1; q < EXPERTS; ++q) if (t >= sMeta[q]) e = q;
        int ti = t - sMeta[e];
        rowStart = sMeta[9 + e] + ti * TILE;
        Mt = min(TILE, sMeta[17 + e] - ti * TILE);
    };
    auto loadW = [&](int e) {
        const float4* Wg  = (const float4*)(W + (size_t)e * D * D);
        float4*       sW4 = (float4*)sW;
        #pragma unroll
        for (int i = tid; i < D * D / 4; i += GBLOCK) sW4[i] = Wg[i];
        if (tid < D) sB[tid] = b[e * D + tid];
    };

    // ---- prologue: stage tile t0 into buffer 0 ----
    int e, rowStart, Mt;
    tileInfo(t0, e, rowStart, Mt);
    loadW(e);
    if (tid < TILE) sT0[tid] = g_perm[rowStart + (tid < Mt ? tid : 0)];
    __syncthreads();
    {
        #pragma unroll
        for (int it = 0; it < 8; ++it) {
            int i = wid * 16 + it * 2 + i2;
            int token = sT0[i];
            const float2* fr = (const float2*)(features + (size_t)token * D);
            float2 vA = fr[c];
            float2 vB = fr[16 + c];
            int g = i >> 2, r = i & 3;
            int gp = ((g ^ sw) << 2) + r;
            sF0[(2*c)      * TILE + gp] = vA.x;
            sF0[(2*c + 1)  * TILE + gp] = vA.y;
            sF0[(32 + 2*c) * TILE + gp] = vB.x;
            sF0[(33 + 2*c) * TILE + gp] = vB.y;
        }
    }
    __syncthreads();

    float* sFc = sF0; float* sFn = sF1;
    int*   sTc = sT0; int*   sTn = sT1;

    const int j0 = wid * 8;

    for (int t = t0; t < t1; ++t) {
        const bool hasNext = (t + 1 < t1);
        int eN = e, rowStartN = 0, MtN = 0, ntok = 0;
        if (hasNext) {
            tileInfo(t + 1, eN, rowStartN, MtN);
            if (tid < TILE)
                ntok = g_perm[rowStartN + (tid < MtN ? tid : 0)];   // [A] in flight
        }

        // init accumulators with bias
        ull acc[4][4];
        {
            const ull* bp = (const ull*)(sB + j0);
            #pragma unroll
            for (int tt = 0; tt < 4; ++tt)
                #pragma unroll
                for (int p = 0; p < 4; ++p) acc[tt][p] = bp[p];
        }

        const float4* sF4  = (const float4*)sFc;
        const float*  wptr = sW + j0;

        // [B] compute k = 0 .. KSPLIT-1 (hides perm LDG)
        #pragma unroll 8
        for (int k = 0; k < KSPLIT; ++k) {
            int   s = (k >> 1) & 7;
            float4 f = sF4[k * (TILE/4) + (lane ^ s)];
            const ulonglong2* wp = (const ulonglong2*)(wptr + k * D);
            ulonglong2 wA = wp[0];
            ulonglong2 wB = wp[1];
            ull fk0 = packf2(f.x), fk1 = packf2(f.y);
            ull fk2 = packf2(f.z), fk3 = packf2(f.w);
            ffma2(acc[0][0], fk0, wA.x); ffma2(acc[0][1], fk0, wA.y);
            ffma2(acc[0][2], fk0, wB.x); ffma2(acc[0][3], fk0, wB.y);
            ffma2(acc[1][0], fk1, wA.x); ffma2(acc[1][1], fk1, wA.y);
            ffma2(acc[1][2], fk1, wB.x); ffma2(acc[1][3], fk1, wB.y);
            ffma2(acc[2][0], fk2, wA.x); ffma2(acc[2][1], fk2, wA.y);
            ffma2(acc[2][2], fk2, wB.x); ffma2(acc[2][3], fk2, wB.y);
            ffma2(acc[3][0], fk3, wA.x); ffma2(acc[3][1], fk3, wA.y);
            ffma2(acc[3][2], fk3, wB.x); ffma2(acc[3][3], fk3, wB.y);
        }

        // [C] publish next token list
        if (hasNext && tid < TILE) sTn[tid] = ntok;
        __syncthreads();   // [D]

        // [E] prefetch next tile's features into registers
        float2 fa[8], fb[8];
        if (hasNext) {
            #pragma unroll
            for (int it = 0; it < 8; ++it) {
                int i = wid * 16 + it * 2 + i2;
                int token = sTn[i];
                const float2* fr = (const float2*)(features + (size_t)token * D);
                fa[it] = fr[c];
                fb[it] = fr[16 + c];
            }
        }

        // [F] compute k = KSPLIT .. D-1 (hides feature LDGs)
        #pragma unroll 8
        for (int k = KSPLIT; k < D; ++k) {
            int   s = (k >> 1) & 7;
            float4 f = sF4[k * (TILE/4) + (lane ^ s)];
            const ulonglong2* wp = (const ulonglong2*)(wptr + k * D);
            ulonglong2 wA = wp[0];
            ulonglong2 wB = wp[1];
            ull fk0 = packf2(f.x), fk1 = packf2(f.y);
            ull fk2 = packf2(f.z), fk3 = packf2(f.w);
            ffma2(acc[0][0], fk0, wA.x); ffma2(acc[0][1], fk0, wA.y);
            ffma2(acc[0][2], fk0, wB.x); ffma2(acc[0][3], fk0, wB.y);
            ffma2(acc[1][0], fk1, wA.x); ffma2(acc[1][1], fk1, wA.y);
            ffma2(acc[1][2], fk1, wB.x); ffma2(acc[1][3], fk1, wB.y);
            ffma2(acc[2][0], fk2, wA.x); ffma2(acc[2][1], fk2, wA.y);
            ffma2(acc[2][2], fk2, wB.x); ffma2(acc[2][3], fk2, wB.y);
            ffma2(acc[3][0], fk3, wA.x); ffma2(acc[3][1], fk3, wA.y);
            ffma2(acc[3][2], fk3, wB.x); ffma2(acc[3][3], fk3, wB.y);
        }

        // [G] stage next tile features into shadow buffer
        if (hasNext) {
            #pragma unroll
            for (int it = 0; it < 8; ++it) {
                int i = wid * 16 + it * 2 + i2;
                int g = i >> 2, r = i & 3;
                int gp = ((g ^ sw) << 2) + r;
                sFn[(2*c)      * TILE + gp] = fa[it].x;
                sFn[(2*c + 1)  * TILE + gp] = fa[it].y;
                sFn[(32 + 2*c) * TILE + gp] = fb[it].x;
                sFn[(33 + 2*c) * TILE + gp] = fb[it].y;
            }
        }

        // [H] store current tile outputs
        {
            const int tb = lane * 4;
            #pragma unroll
            for (int tt = 0; tt < 4; ++tt) {
                int i = tb + tt;
                if (i < Mt) {
                    int token = sTc[i];
                    float2 a0 = unpack2(acc[tt][0]), a1 = unpack2(acc[tt][1]);
                    float2 a2 = unpack2(acc[tt][2]), a3 = unpack2(acc[tt][3]);
                    float4* orow = (float4*)(out + (size_t)token * D + j0);
                    orow[0] = make_float4(a0.x, a0.y, a1.x, a1.y);
                    orow[1] = make_float4(a2.x, a2.y, a3.x, a3.y);
                }
            }
        }

        // [I] expert change: reload weights (uniform condition)
        if (hasNext && eN != e) {
            __syncthreads();
            loadW(eN);
        }
        __syncthreads();   // [J] shadow buffers ready; sW/sB consistent

        e = eN; Mt = MtN;
        float* ft = sFc; sFc = sFn; sFn = ft;
        int*   it_ = sTc; sTc = sTn; sTn = it_;
    }
}

// ---------------- launch ----------------
extern "C" void kernel_launch(void* const* d_in, const int* in_sizes, int n_in,
                              void* d_out, int out_size) {
    const float* features = (const float*)d_in[0];
    const int*   inds     = (const int*)d_in[1];
    const float* W        = (const float*)d_in[2];
    const float* b        = (const float*)d_in[3];
    float*       out      = (float*)d_out;

    int N = in_sizes[0] / D;

    (void)cudaFuncSetAttribute(gemm_kernel,
                               cudaFuncAttributeMaxDynamicSharedMemorySize,
                               GSMEM_BYTES);

    int nScan = (N + SCAN_TOKENS - 1) / SCAN_TOKENS;
    count_kernel<<<nScan, SCAN_TPB>>>(inds, N);
    scan_kernel<<<1, NUM_SCAN_CTAS>>>();
    scatter_kernel<<<nScan, SCAN_TPB>>>(inds, N);
    gemm_kernel<<<NCTA_GEMM, GBLOCK, GSMEM_BYTES>>>(features, W, b, out);
}

// round 10
// speedup vs baseline: 2.2651x; 1.2018x over previous
#include <cuda_runtime.h>
#include <cuda_bf16.h>
#include <cstdint>

#define D        64
#define EXPERTS  8
#define NTOK     (1 << 20)
#define SCAN_TPB 256
#define SCAN_TOKENS 4096
#define NUM_SCAN_CTAS (NTOK / SCAN_TOKENS)   // 256
#define TILE     128
#define GBLOCK   128
#define NCTA_GEMM 592

#if defined(__CUDA_ARCH_FEAT_SM103_ALL) || \
    (defined(__CUDA_ARCH_SPECIFIC__) && (__CUDA_ARCH_SPECIFIC__ == 1030))
#define TCGEN_OK 1
#else
#define TCGEN_OK 0
#endif

// idesc kind::f16: dtype F32(1<<4) | atype BF16(1<<7) | btype BF16(1<<10)
//                  | (N/8)<<17 | (M/16)<<24   => M=128,N=64
#define IDESC_BF16 0x8100490u

// smem offsets from 1KB-aligned base
#define OFF_AH   0        // A hi: 128 rows x 128B (SW128)
#define OFF_AL   16384    // A lo
#define OFF_BH   32768    // B hi: 64 rows x 128B
#define OFF_BL   40960    // B lo
#define OFF_BIAS 49152    // 64 floats
#define OFF_MBAR 49408    // 8 B
#define OFF_TMEM 49416    // 4 B
#define OFF_META 49424    // 25 ints
#define OFF_TICK 49524    // 1 int
#define SMEM_SZ  (49536 + 1024)

// ---------------- device scratch ----------------
__device__ int g_perm[NTOK];
__device__ int g_blockCnt[NUM_SCAN_CTAS * EXPERTS];
__device__ int g_blockBase[NUM_SCAN_CTAS * EXPERTS];
__device__ int g_cnt[EXPERTS];
__device__ int g_off[EXPERTS + 1];
__device__ int g_tileOfs[EXPERTS + 1];
__device__ int g_ticket;

// ---------------- PTX helpers ----------------
__device__ __forceinline__ uint32_t smem_u32(const void* p) {
    uint32_t a;
    asm("{ .reg .u64 t; cvta.to.shared.u64 t, %1; cvt.u32.u64 %0, t; }"
        : "=r"(a) : "l"(p));
    return a;
}
__device__ __forceinline__ uint32_t bits2(__nv_bfloat162 h) {
    return *reinterpret_cast<uint32_t*>(&h);
}

#if TCGEN_OK
__device__ __forceinline__ uint32_t elect_one_pred() {
    uint32_t p;
    asm volatile("{\n\t.reg .pred p;\n\telect.sync _|p, 0xFFFFFFFF;\n\t"
                 "selp.b32 %0, 1, 0, p;\n\t}" : "=r"(p));
    return p;
}
__device__ __forceinline__ uint64_t make_desc(uint32_t addr) {
    // SW128 (layout 2), Blackwell version=1, SBO=64 (1024B atom), LBO=1 (16B)
    const uint64_t base = (2ull << 61) | (1ull << 46) | (64ull << 32) | (1ull << 16);
    return base | ((uint64_t)(addr >> 4) & 0x3FFF);
}
__device__ __forceinline__ void mma_f16_ss(uint32_t d_tmem, uint64_t a_desc,
                                           uint64_t b_desc, uint32_t idesc,
                                           uint32_t accum) {
    asm volatile(
        "{\n\t.reg .pred p;\n\tsetp.ne.u32 p, %5, 0;\n\t"
        "tcgen05.mma.cta_group::1.kind::f16 [%0], %1, %2, %3, {%4, %4, %4, %4}, p;\n\t}"
        :: "r"(d_tmem), "l"(a_desc), "l"(b_desc), "r"(idesc), "r"(0u), "r"(accum)
        : "memory");
}
__device__ __forceinline__ void mbar_wait(uint32_t mbar, uint32_t parity) {
    asm volatile(
        "{\n\t.reg .pred P;\n\t"
        "WL_%=:\n\t"
        "mbarrier.try_wait.parity.acquire.cta.shared::cta.b64 P, [%0], %1, 0x989680;\n\t"
        "@P bra.uni WD_%=;\n\t"
        "bra.uni WL_%=;\n\t"
        "WD_%=:\n\t}"
        :: "r"(mbar), "r"(parity) : "memory");
}
#define LDTM_X32(r, addr) \
    asm volatile( \
        "tcgen05.ld.sync.aligned.32x32b.x32.b32 " \
        "{%0, %1, %2, %3, %4, %5, %6, %7, " \
        " %8, %9, %10, %11, %12, %13, %14, %15, " \
        " %16, %17, %18, %19, %20, %21, %22, %23, " \
        " %24, %25, %26, %27, %28, %29, %30, %31}, [%32];" \
        : "=r"((r)[0]),  "=r"((r)[1]),  "=r"((r)[2]),  "=r"((r)[3]), \
          "=r"((r)[4]),  "=r"((r)[5]),  "=r"((r)[6]),  "=r"((r)[7]), \
          "=r"((r)[8]),  "=r"((r)[9]),  "=r"((r)[10]), "=r"((r)[11]), \
          "=r"((r)[12]), "=r"((r)[13]), "=r"((r)[14]), "=r"((r)[15]), \
          "=r"((r)[16]), "=r"((r)[17]), "=r"((r)[18]), "=r"((r)[19]), \
          "=r"((r)[20]), "=r"((r)[21]), "=r"((r)[22]), "=r"((r)[23]), \
          "=r"((r)[24]), "=r"((r)[25]), "=r"((r)[26]), "=r"((r)[27]), \
          "=r"((r)[28]), "=r"((r)[29]), "=r"((r)[30]), "=r"((r)[31]) \
        : "r"(addr))
#endif  // TCGEN_OK

// ---------------- kernel A: per-CTA histogram ----------------
__global__ __launch_bounds__(SCAN_TPB)
void count_kernel(const int* __restrict__ inds, int N) {
    const int cta = blockIdx.x, tid = threadIdx.x;
    const int base = cta * SCAN_TOKENS;
    int c[EXPERTS];
    #pragma unroll
    for (int q = 0; q < EXPERTS; ++q) c[q] = 0;
    for (int i = tid; i < SCAN_TOKENS; i += SCAN_TPB) {
        int g = base + i;
        if (g < N) {
            int e = inds[g];
            #pragma unroll
            for (int q = 0; q < EXPERTS; ++q) c[q] += (e == q);
        }
    }
    #pragma unroll
    for (int q = 0; q < EXPERTS; ++q)
        c[q] = __reduce_add_sync(0xffffffffu, c[q]);
    __shared__ int w[SCAN_TPB / 32][EXPERTS];
    if ((tid & 31) == 0) {
        #pragma unroll
        for (int q = 0; q < EXPERTS; ++q) w[tid >> 5][q] = c[q];
    }
    __syncthreads();
    if (tid < EXPERTS) {
        int s = 0;
        #pragma unroll
        for (int ww = 0; ww < SCAN_TPB / 32; ++ww) s += w[ww][tid];
        g_blockCnt[cta * EXPERTS + tid] = s;
    }
}

// ---------------- kernel B: scan (1 CTA) ----------------
__global__ __launch_bounds__(NUM_SCAN_CTAS)
void scan_kernel() {
    __shared__ int s[NUM_SCAN_CTAS];
    __shared__ int sTot[EXPERTS];
    const int tid = threadIdx.x;
    if (tid == 0) g_ticket = 0;
    for (int e = 0; e < EXPERTS; ++e) {
        int v = g_blockCnt[tid * EXPERTS + e];
        s[tid] = v;
        __syncthreads();
        for (int ofs = 1; ofs < NUM_SCAN_CTAS; ofs <<= 1) {
            int t = (tid >= ofs) ? s[tid - ofs] : 0;
            __syncthreads();
            s[tid] += t;
            __syncthreads();
        }
        if (tid == NUM_SCAN_CTAS - 1) sTot[e] = s[tid];
        g_blockBase[tid * EXPERTS + e] = s[tid] - v;
        __syncthreads();
    }
    if (tid == 0) {
        int off = 0, tofs = 0;
        for (int e = 0; e < EXPERTS; ++e) {
            g_cnt[e] = sTot[e];
            g_off[e] = off;
            g_tileOfs[e] = tofs;
            off  += sTot[e];
            tofs += (sTot[e] + TILE - 1) / TILE;
        }
        g_off[EXPERTS] = off;
        g_tileOfs[EXPERTS] = tofs;
    }
    __syncthreads();
    #pragma unroll
    for (int e = 0; e < EXPERTS; ++e)
        g_blockBase[tid * EXPERTS + e] += g_off[e];
}

// ---------------- kernel C: scatter token ids ----------------
__global__ __launch_bounds__(SCAN_TPB)
void scatter_kernel(const int* __restrict__ inds, int N) {
    __shared__ int ctr[EXPERTS];
    const int cta = blockIdx.x, tid = threadIdx.x;
    if (tid < EXPERTS) ctr[tid] = g_blockBase[cta * EXPERTS + tid];
    __syncthreads();
    const int base = cta * SCAN_TOKENS;
    for (int i = tid; i < SCAN_TOKENS; i += SCAN_TPB) {
        int g = base + i;
        if (g < N) {
            int e = inds[g];
            int slot = atomicAdd(&ctr[e], 1);
            g_perm[slot] = g;
        }
    }
}

// ---------------- kernel D: tcgen05 bf16-split GEMM (persistent, work-stealing) ----------------
extern __shared__ char dsm[];

__global__ __launch_bounds__(GBLOCK)
void gemm_kernel(const float* __restrict__ features,
                 const float* __restrict__ W,
                 const float* __restrict__ b,
                 float* __restrict__ out)
{
    char* base = (char*)(((uintptr_t)dsm + 1023) & ~(uintptr_t)1023);
    int*   sMeta = (int*)(base + OFF_META);
    int*   sTick = (int*)(base + OFF_TICK);

    const int tid = threadIdx.x;
    const int row = tid;                 // token row 0..127 (= TMEM lane)

    if (tid < 9)       sMeta[tid] = g_tileOfs[tid];
    else if (tid < 17) sMeta[tid] = g_off[tid - 9];
    else if (tid < 25) sMeta[tid] = g_cnt[tid - 17];

#if TCGEN_OK
    float* sB = (float*)(base + OFF_BIAS);
    const uint32_t sbase = smem_u32(base);
    const uint32_t mbar  = sbase + OFF_MBAR;
    const int wid = tid >> 5;

    if (tid == 0)
        asm volatile("mbarrier.init.shared.b64 [%0], 1;" :: "r"(mbar) : "memory");
    if (wid == 0)
        asm volatile("tcgen05.alloc.cta_group::1.sync.aligned.shared::cta.b32 [%0], 64;"
                     :: "r"(sbase + OFF_TMEM) : "memory");
    __syncthreads();
    uint32_t tmem;
    asm volatile("ld.shared.b32 %0, [%1];" : "=r"(tmem) : "r"(sbase + OFF_TMEM));
    if (wid == 0)
        asm volatile("tcgen05.relinquish_alloc_permit.cta_group::1.sync.aligned;");

    const uint64_t dAH = make_desc(sbase + OFF_AH);
    const uint64_t dAL = make_desc(sbase + OFF_AL);
    const uint64_t dBH = make_desc(sbase + OFF_BH);
    const uint64_t dBL = make_desc(sbase + OFF_BL);

    const int totalTiles = sMeta[8];
    uint32_t ph = 0;
    int eCur = -1;

    for (;;) {
        if (tid == 0) *sTick = atomicAdd(&g_ticket, 1);
        __syncthreads();                         // [1] also frees smem from prev tile
        const int t = *sTick;
        if (t >= totalTiles) break;

        // tile info (uniform)
        int e = 0;
        #pragma unroll
        for (int q = 1; q < EXPERTS; ++q) if (t >= sMeta[q]) e = q;
        const int ti = t - sMeta[e];
        const int rowStart = sMeta[9 + e] + ti * TILE;
        const int Mt = min(TILE, sMeta[17 + e] - ti * TILE);

        // gather own row (256B, 16 independent LDG.128)
        const int tok = g_perm[rowStart + (row < Mt ? row : 0)];
        const float4* frow = (const float4*)(features + (size_t)tok * D);
        float4 v[16];
        #pragma unroll
        for (int i = 0; i < 16; ++i) v[i] = frow[i];

        // expert weight tiles (transpose + bf16 split), rare
        if (e != eCur) {
            const int j  = tid >> 1;             // B row (output col) 0..63
            const int kh = (tid & 1) * 32;       // k half
            const float* wcol = W + (size_t)e * D * D + j;
            float wv[32];
            #pragma unroll
            for (int k = 0; k < 32; ++k) wv[k] = wcol[(size_t)(kh + k) * D];
            #pragma unroll
            for (int c = 0; c < 4; ++c) {        // 16B chunks of the row
                uint32_t hb[4], lb[4];
                #pragma unroll
                for (int p = 0; p < 4; ++p) {
                    float x0 = wv[c * 8 + 2 * p], x1 = wv[c * 8 + 2 * p + 1];
                    __nv_bfloat162 h = __floats2bfloat162_rn(x0, x1);
                    float2 hf = __bfloat1622float2(h);
                    __nv_bfloat162 l = __floats2bfloat162_rn(x0 - hf.x, x1 - hf.y);
                    hb[p] = bits2(h); lb[p] = bits2(l);
                }
                uint32_t off = (uint32_t)j * 128u + (uint32_t)(kh + c * 8) * 2u;
                uint32_t sw  = off ^ ((off >> 3) & 0x70);
                *(uint4*)(base + OFF_BH + sw) = make_uint4(hb[0], hb[1], hb[2], hb[3]);
                *(uint4*)(base + OFF_BL + sw) = make_uint4(lb[0], lb[1], lb[2], lb[3]);
            }
            if (tid < D) sB[tid] = b[e * D + tid];
            eCur = e;
        }

        // convert features -> bf16 hi/lo, STS (SW128 K-major rows of 128B)
        {
            const uint32_t aoff = (uint32_t)row * 128u;
            #pragma unroll
            for (int c = 0; c < 8; ++c) {
                float4 fa = v[2 * c], fb = v[2 * c + 1];
                __nv_bfloat162 h0 = __floats2bfloat162_rn(fa.x, fa.y);
                __nv_bfloat162 h1 = __floats2bfloat162_rn(fa.z, fa.w);
                __nv_bfloat162 h2 = __floats2bfloat162_rn(fb.x, fb.y);
                __nv_bfloat162 h3 = __floats2bfloat162_rn(fb.z, fb.w);
                float2 f0 = __bfloat1622float2(h0), f1 = __bfloat1622float2(h1);
                float2 f2 = __bfloat1622float2(h2), f3 = __bfloat1622float2(h3);
                __nv_bfloat162 l0 = __floats2bfloat162_rn(fa.x - f0.x, fa.y - f0.y);
                __nv_bfloat162 l1 = __floats2bfloat162_rn(fa.z - f1.x, fa.w - f1.y);
                __nv_bfloat162 l2 = __floats2bfloat162_rn(fb.x - f2.x, fb.y - f2.y);
                __nv_bfloat162 l3 = __floats2bfloat162_rn(fb.z - f3.x, fb.w - f3.y);
                uint32_t off = aoff + c * 16u;
                uint32_t sw  = off ^ ((off >> 3) & 0x70);
                *(uint4*)(base + OFF_AH + sw) =
                    make_uint4(bits2(h0), bits2(h1), bits2(h2), bits2(h3));
                *(uint4*)(base + OFF_AL + sw) =
                    make_uint4(bits2(l0), bits2(l1), bits2(l2), bits2(l3));
            }
        }
        asm volatile("fence.proxy.async.shared::cta;" ::: "memory");
        __syncthreads();                         // [2] tiles staged, visible to MMA

        // MMA: D = Ah@Bh + Ah@Bl + Al@Bh   (12 UTCHMMA, K=16 each)
        if (wid == 0 && elect_one_pred()) {
            #pragma unroll
            for (int k = 0; k < 4; ++k)
                mma_f16_ss(tmem, dAH + 2 * k, dBH + 2 * k, IDESC_BF16, k > 0);
            #pragma unroll
            for (int k = 0; k < 4; ++k)
                mma_f16_ss(tmem, dAH + 2 * k, dBL + 2 * k, IDESC_BF16, 1);
            #pragma unroll
            for (int k = 0; k < 4; ++k)
                mma_f16_ss(tmem, dAL + 2 * k, dBH + 2 * k, IDESC_BF16, 1);
            asm volatile(
                "tcgen05.commit.cta_group::1.mbarrier::arrive::one.shared::cluster.b64 [%0];"
                :: "r"(mbar) : "memory");
        }

        mbar_wait(mbar, ph);
        ph ^= 1;
        asm volatile("tcgen05.fence::after_thread_sync;" ::: "memory");

        // epilogue: LDTM 64 fp32 cols, add bias, scatter-store own row
        uint32_t dr[32], dr2[32];
        LDTM_X32(dr,  tmem);
        LDTM_X32(dr2, tmem + 32);
        asm volatile("tcgen05.wait::ld.sync.aligned;" ::: "memory");

        if (row < Mt) {
            float4* orow = (float4*)(out + (size_t)tok * D);
            #pragma unroll
            for (int q = 0; q < 16; ++q) {
                const uint32_t* s = (q < 8) ? &dr[q * 4] : &dr2[(q - 8) * 4];
                float4 bb = *(const float4*)(sB + q * 4);
                float4 o;
                o.x = __uint_as_float(s[0]) + bb.x;
                o.y = __uint_as_float(s[1]) + bb.y;
                o.z = __uint_as_float(s[2]) + bb.z;
                o.w = __uint_as_float(s[3]) + bb.w;
                orow[q] = o;
            }
        }
        asm volatile("tcgen05.fence::before_thread_sync;" ::: "memory");
    }

    __syncthreads();
    if (tid == 0)
        asm volatile("mbarrier.inval.shared.b64 [%0];" :: "r"(mbar) : "memory");
    __syncthreads();
    if (wid == 0)
        asm volatile("tcgen05.dealloc.cta_group::1.sync.aligned.b32 %0, 64;"
                     :: "r"(tmem));

#else   // !TCGEN_OK — generic-PTX fallback (compiles everywhere; sm_103a cubin is used at runtime)
    __syncthreads();
    const int totalTiles = sMeta[8];
    for (;;) {
        if (tid == 0) *sTick = atomicAdd(&g_ticket, 1);
        __syncthreads();
        const int t = *sTick;
        if (t >= totalTiles) break;

        int e = 0;
        #pragma unroll
        for (int q = 1; q < EXPERTS; ++q) if (t >= sMeta[q]) e = q;
        const int ti = t - sMeta[e];
        const int rowStart = sMeta[9 + e] + ti * TILE;
        const int Mt = min(TILE, sMeta[17 + e] - ti * TILE);

        const int tok = g_perm[rowStart + (row < Mt ? row : 0)];
        const float* frow = features + (size_t)tok * D;
        float v[D];
        #pragma unroll
        for (int k = 0; k < D; ++k) v[k] = frow[k];

        if (row < Mt) {
            const float* We = W + (size_t)e * D * D;
            for (int j = 0; j < D; ++j) {
                float s = b[e * D + j];
                #pragma unroll 16
                for (int k = 0; k < D; ++k) s = fmaf(v[k], We[(size_t)k * D + j], s);
                out[(size_t)tok * D + j] = s;
            }
        }
        __syncthreads();
    }
#endif
}

// ---------------- launch ----------------
extern "C" void kernel_launch(void* const* d_in, const int* in_sizes, int n_in,
                              void* d_out, int out_size) {
    const float* features = (const float*)d_in[0];
    const int*   inds     = (const int*)d_in[1];
    const float* W        = (const float*)d_in[2];
    const float* b        = (const float*)d_in[3];
    float*       out      = (float*)d_out;

    int N = in_sizes[0] / D;

    (void)cudaFuncSetAttribute(gemm_kernel,
                               cudaFuncAttributeMaxDynamicSharedMemorySize,
                               SMEM_SZ);

    int nScan = (N + SCAN_TOKENS - 1) / SCAN_TOKENS;
    count_kernel<<<nScan, SCAN_TPB>>>(inds, N);
    scan_kernel<<<1, NUM_SCAN_CTAS>>>();
    scatter_kernel<<<nScan, SCAN_TPB>>>(inds, N);
    gemm_kernel<<<NCTA_GEMM, GBLOCK, SMEM_SZ>>>(features, W, b, out);
}

// round 11
// speedup vs baseline: 2.3711x; 1.0468x over previous
#include <cuda_runtime.h>
#include <cuda_bf16.h>
#include <cstdint>

#define D        64
#define EXPERTS  8
#define NTOK     (1 << 20)
#define SCAN_TPB 256
#define SCAN_TOKENS 4096
#define NUM_SCAN_CTAS (NTOK / SCAN_TOKENS)   // 256
#define TILE     128
#define GBLOCK   128
#define NCTA_GEMM 296

#if defined(__CUDA_ARCH_FEAT_SM103_ALL) || \
    (defined(__CUDA_ARCH_SPECIFIC__) && (__CUDA_ARCH_SPECIFIC__ == 1030))
#define TCGEN_OK 1
#else
#define TCGEN_OK 0
#endif

// idesc kind::f16: dtype F32(1<<4) | atype BF16(1<<7) | btype BF16(1<<10)
//                  | (N/8)<<17 | (M/16)<<24   => M=128,N=64
#define IDESC_BF16 0x8100490u

// smem offsets from 1KB-aligned base (A double-buffered)
#define OFF_A0H  0        // 128 x 128B SW128
#define OFF_A0L  16384
#define OFF_A1H  32768
#define OFF_A1L  49152
#define OFF_BH   65536    // 64 x 128B
#define OFF_BL   73728
#define OFF_BIAS 81920    // 64 floats
#define OFF_MBAR 82176    // 2 x 8B
#define OFF_TMEM 82200    // 4B
#define OFF_META 82208    // 25 ints
#define OFF_TICK 82308    // 1 int
#define SMEM_SZ  (82312 + 1024)

// ---------------- device scratch ----------------
__device__ int g_perm[NTOK];
__device__ int g_blockCnt[NUM_SCAN_CTAS * EXPERTS];
__device__ int g_blockBase[NUM_SCAN_CTAS * EXPERTS];
__device__ int g_cnt[EXPERTS];
__device__ int g_off[EXPERTS + 1];
__device__ int g_tileOfs[EXPERTS + 1];
__device__ int g_ticket;

// ---------------- helpers ----------------
__device__ __forceinline__ uint32_t smem_u32(const void* p) {
    uint32_t a;
    asm("{ .reg .u64 t; cvta.to.shared.u64 t, %1; cvt.u32.u64 %0, t; }"
        : "=r"(a) : "l"(p));
    return a;
}
__device__ __forceinline__ uint32_t bits2(__nv_bfloat162 h) {
    return *reinterpret_cast<uint32_t*>(&h);
}

#if TCGEN_OK
__device__ __forceinline__ uint32_t elect_one_pred() {
    uint32_t p;
    asm volatile("{\n\t.reg .pred p;\n\telect.sync _|p, 0xFFFFFFFF;\n\t"
                 "selp.b32 %0, 1, 0, p;\n\t}" : "=r"(p));
    return p;
}
__device__ __forceinline__ uint64_t make_desc(uint32_t addr) {
    // SW128 (layout 2), Blackwell version=1, SBO=64, LBO=1
    const uint64_t base = (2ull << 61) | (1ull << 46) | (64ull << 32) | (1ull << 16);
    return base | ((uint64_t)(addr >> 4) & 0x3FFF);
}
__device__ __forceinline__ void mma_f16_ss(uint32_t d_tmem, uint64_t a_desc,
                                           uint64_t b_desc, uint32_t idesc,
                                           uint32_t accum) {
    asm volatile(
        "{\n\t.reg .pred p;\n\tsetp.ne.u32 p, %5, 0;\n\t"
        "tcgen05.mma.cta_group::1.kind::f16 [%0], %1, %2, %3, {%4, %4, %4, %4}, p;\n\t}"
        :: "r"(d_tmem), "l"(a_desc), "l"(b_desc), "r"(idesc), "r"(0u), "r"(accum)
        : "memory");
}
__device__ __forceinline__ void mbar_wait(uint32_t mbar, uint32_t parity) {
    asm volatile(
        "{\n\t.reg .pred P;\n\t"
        "WL_%=:\n\t"
        "mbarrier.try_wait.parity.acquire.cta.shared::cta.b64 P, [%0], %1, 0x989680;\n\t"
        "@P bra.uni WD_%=;\n\t"
        "bra.uni WL_%=;\n\t"
        "WD_%=:\n\t}"
        :: "r"(mbar), "r"(parity) : "memory");
}
#define LDTM_X32(r, addr) \
    asm volatile( \
        "tcgen05.ld.sync.aligned.32x32b.x32.b32 " \
        "{%0, %1, %2, %3, %4, %5, %6, %7, " \
        " %8, %9, %10, %11, %12, %13, %14, %15, " \
        " %16, %17, %18, %19, %20, %21, %22, %23, " \
        " %24, %25, %26, %27, %28, %29, %30, %31}, [%32];" \
        : "=r"((r)[0]),  "=r"((r)[1]),  "=r"((r)[2]),  "=r"((r)[3]), \
          "=r"((r)[4]),  "=r"((r)[5]),  "=r"((r)[6]),  "=r"((r)[7]), \
          "=r"((r)[8]),  "=r"((r)[9]),  "=r"((r)[10]), "=r"((r)[11]), \
          "=r"((r)[12]), "=r"((r)[13]), "=r"((r)[14]), "=r"((r)[15]), \
          "=r"((r)[16]), "=r"((r)[17]), "=r"((r)[18]), "=r"((r)[19]), \
          "=r"((r)[20]), "=r"((r)[21]), "=r"((r)[22]), "=r"((r)[23]), \
          "=r"((r)[24]), "=r"((r)[25]), "=r"((r)[26]), "=r"((r)[27]), \
          "=r"((r)[28]), "=r"((r)[29]), "=r"((r)[30]), "=r"((r)[31]) \
        : "r"(addr))
#endif  // TCGEN_OK

// ---------------- kernel A: per-CTA histogram ----------------
__global__ __launch_bounds__(SCAN_TPB)
void count_kernel(const int* __restrict__ inds, int N) {
    const int cta = blockIdx.x, tid = threadIdx.x;
    const int base = cta * SCAN_TOKENS;
    int c[EXPERTS];
    #pragma unroll
    for (int q = 0; q < EXPERTS; ++q) c[q] = 0;
    for (int i = tid; i < SCAN_TOKENS; i += SCAN_TPB) {
        int g = base + i;
        if (g < N) {
            int e = inds[g];
            #pragma unroll
            for (int q = 0; q < EXPERTS; ++q) c[q] += (e == q);
        }
    }
    #pragma unroll
    for (int q = 0; q < EXPERTS; ++q)
        c[q] = __reduce_add_sync(0xffffffffu, c[q]);
    __shared__ int w[SCAN_TPB / 32][EXPERTS];
    if ((tid & 31) == 0) {
        #pragma unroll
        for (int q = 0; q < EXPERTS; ++q) w[tid >> 5][q] = c[q];
    }
    __syncthreads();
    if (tid < EXPERTS) {
        int s = 0;
        #pragma unroll
        for (int ww = 0; ww < SCAN_TPB / 32; ++ww) s += w[ww][tid];
        g_blockCnt[cta * EXPERTS + tid] = s;
    }
}

// ---------------- kernel B: scan (1 CTA) ----------------
__global__ __launch_bounds__(NUM_SCAN_CTAS)
void scan_kernel() {
    __shared__ int s[NUM_SCAN_CTAS];
    __shared__ int sTot[EXPERTS];
    const int tid = threadIdx.x;
    if (tid == 0) g_ticket = 0;
    for (int e = 0; e < EXPERTS; ++e) {
        int v = g_blockCnt[tid * EXPERTS + e];
        s[tid] = v;
        __syncthreads();
        for (int ofs = 1; ofs < NUM_SCAN_CTAS; ofs <<= 1) {
            int t = (tid >= ofs) ? s[tid - ofs] : 0;
            __syncthreads();
            s[tid] += t;
            __syncthreads();
        }
        if (tid == NUM_SCAN_CTAS - 1) sTot[e] = s[tid];
        g_blockBase[tid * EXPERTS + e] = s[tid] - v;
        __syncthreads();
    }
    if (tid == 0) {
        int off = 0, tofs = 0;
        for (int e = 0; e < EXPERTS; ++e) {
            g_cnt[e] = sTot[e];
            g_off[e] = off;
            g_tileOfs[e] = tofs;
            off  += sTot[e];
            tofs += (sTot[e] + TILE - 1) / TILE;
        }
        g_off[EXPERTS] = off;
        g_tileOfs[EXPERTS] = tofs;
    }
    __syncthreads();
    #pragma unroll
    for (int e = 0; e < EXPERTS; ++e)
        g_blockBase[tid * EXPERTS + e] += g_off[e];
}

// ---------------- kernel C: scatter token ids ----------------
__global__ __launch_bounds__(SCAN_TPB)
void scatter_kernel(const int* __restrict__ inds, int N) {
    __shared__ int ctr[EXPERTS];
    const int cta = blockIdx.x, tid = threadIdx.x;
    if (tid < EXPERTS) ctr[tid] = g_blockBase[cta * EXPERTS + tid];
    __syncthreads();
    const int base = cta * SCAN_TOKENS;
    for (int i = tid; i < SCAN_TOKENS; i += SCAN_TPB) {
        int g = base + i;
        if (g < N) {
            int e = inds[g];
            int slot = atomicAdd(&ctr[e], 1);
            g_perm[slot] = g;
        }
    }
}

// ---------------- kernel D: pipelined tcgen05 bf16-split GEMM ----------------
extern __shared__ char dsm[];

__global__ __launch_bounds__(GBLOCK)
void gemm_kernel(const float* __restrict__ features,
                 const float* __restrict__ W,
                 const float* __restrict__ b,
                 float* __restrict__ out)
{
    char* base = (char*)(((uintptr_t)dsm + 1023) & ~(uintptr_t)1023);
    int*   sMeta = (int*)(base + OFF_META);
    int*   sTick = (int*)(base + OFF_TICK);

    const int tid = threadIdx.x;
    const int row = tid;                 // token row 0..127 (= TMEM lane)

    if (tid < 9)       sMeta[tid] = g_tileOfs[tid];
    else if (tid < 17) sMeta[tid] = g_off[tid - 9];
    else if (tid < 25) sMeta[tid] = g_cnt[tid - 17];

#if TCGEN_OK
    float* sB = (float*)(base + OFF_BIAS);
    const uint32_t sbase = smem_u32(base);
    const uint32_t mbar0 = sbase + OFF_MBAR;
    const uint32_t mbar1 = sbase + OFF_MBAR + 8;
    const int wid = tid >> 5;

    if (tid == 0) {
        asm volatile("mbarrier.init.shared.b64 [%0], 1;" :: "r"(mbar0) : "memory");
        asm volatile("mbarrier.init.shared.b64 [%0], 1;" :: "r"(mbar1) : "memory");
    }
    if (wid == 0)
        asm volatile("tcgen05.alloc.cta_group::1.sync.aligned.shared::cta.b32 [%0], 128;"
                     :: "r"(sbase + OFF_TMEM) : "memory");
    __syncthreads();
    uint32_t tmem;
    asm volatile("ld.shared.b32 %0, [%1];" : "=r"(tmem) : "r"(sbase + OFF_TMEM));
    if (wid == 0)
        asm volatile("tcgen05.relinquish_alloc_permit.cta_group::1.sync.aligned;");

    const int totalTiles = sMeta[8];
    int eCur = -1;
    uint32_t ph0 = 0, ph1 = 0;

    // per-fetch state
    int e = 0, tok = 0, Mt = 0;
    float4 v[16];

    // fetch tile t: expert/token info + gather own feature row
    auto fetchTile = [&](int t) {
        e = 0;
        #pragma unroll
        for (int q = 1; q < EXPERTS; ++q) if (t >= sMeta[q]) e = q;
        const int ti = t - sMeta[e];
        const int rowStart = sMeta[9 + e] + ti * TILE;
        Mt = min(TILE, sMeta[17 + e] - ti * TILE);
        tok = g_perm[rowStart + (row < Mt ? row : 0)];
        const float4* frow = (const float4*)(features + (size_t)tok * D);
        #pragma unroll
        for (int i = 0; i < 16; ++i) v[i] = frow[i];
    };

    // stage expert weights (transpose + bf16 split) — rare
    auto loadB = [&]() {
        const int j  = tid >> 1;             // output col 0..63
        const int kh = (tid & 1) * 32;       // k half
        const float* wcol = W + (size_t)e * D * D + j;
        float wv[32];
        #pragma unroll
        for (int k = 0; k < 32; ++k) wv[k] = wcol[(size_t)(kh + k) * D];
        #pragma unroll
        for (int c = 0; c < 4; ++c) {
            uint32_t hb[4], lb[4];
            #pragma unroll
            for (int p = 0; p < 4; ++p) {
                float x0 = wv[c * 8 + 2 * p], x1 = wv[c * 8 + 2 * p + 1];
                __nv_bfloat162 h = __floats2bfloat162_rn(x0, x1);
                float2 hf = __bfloat1622float2(h);
                __nv_bfloat162 l = __floats2bfloat162_rn(x0 - hf.x, x1 - hf.y);
                hb[p] = bits2(h); lb[p] = bits2(l);
            }
            uint32_t off = (uint32_t)j * 128u + (uint32_t)(kh + c * 8) * 2u;
            uint32_t sw  = off ^ ((off >> 3) & 0x70);
            *(uint4*)(base + OFF_BH + sw) = make_uint4(hb[0], hb[1], hb[2], hb[3]);
            *(uint4*)(base + OFF_BL + sw) = make_uint4(lb[0], lb[1], lb[2], lb[3]);
        }
        if (tid < D) sB[tid] = b[e * D + tid];
    };

    // convert gathered row -> bf16 hi/lo into A buffer pb
    auto stageA = [&](int pb) {
        char* ah = base + (pb ? OFF_A1H : OFF_A0H);
        char* al = base + (pb ? OFF_A1L : OFF_A0L);
        const uint32_t aoff = (uint32_t)row * 128u;
        #pragma unroll
        for (int c = 0; c < 8; ++c) {
            float4 fa = v[2 * c], fb = v[2 * c + 1];
            __nv_bfloat162 h0 = __floats2bfloat162_rn(fa.x, fa.y);
            __nv_bfloat162 h1 = __floats2bfloat162_rn(fa.z, fa.w);
            __nv_bfloat162 h2 = __floats2bfloat162_rn(fb.x, fb.y);
            __nv_bfloat162 h3 = __floats2bfloat162_rn(fb.z, fb.w);
            float2 f0 = __bfloat1622float2(h0), f1 = __bfloat1622float2(h1);
            float2 f2 = __bfloat1622float2(h2), f3 = __bfloat1622float2(h3);
            __nv_bfloat162 l0 = __floats2bfloat162_rn(fa.x - f0.x, fa.y - f0.y);
            __nv_bfloat162 l1 = __floats2bfloat162_rn(fa.z - f1.x, fa.w - f1.y);
            __nv_bfloat162 l2 = __floats2bfloat162_rn(fb.x - f2.x, fb.y - f2.y);
            __nv_bfloat162 l3 = __floats2bfloat162_rn(fb.z - f3.x, fb.w - f3.y);
            uint32_t off = aoff + c * 16u;
            uint32_t sw  = off ^ ((off >> 3) & 0x70);
            *(uint4*)(ah + sw) = make_uint4(bits2(h0), bits2(h1), bits2(h2), bits2(h3));
            *(uint4*)(al + sw) = make_uint4(bits2(l0), bits2(l1), bits2(l2), bits2(l3));
        }
    };

    // issue 12 MMAs for buffer pb into tmem accumulator pb; commit to its mbar
    auto issueMMA = [&](int pb) {
        if (wid == 0 && elect_one_pred()) {
            const uint64_t dAH = make_desc(sbase + (pb ? OFF_A1H : OFF_A0H));
            const uint64_t dAL = make_desc(sbase + (pb ? OFF_A1L : OFF_A0L));
            const uint64_t dBH = make_desc(sbase + OFF_BH);
            const uint64_t dBL = make_desc(sbase + OFF_BL);
            const uint32_t acc = tmem + pb * 64;
            #pragma unroll
            for (int k = 0; k < 4; ++k)
                mma_f16_ss(acc, dAH + 2 * k, dBH + 2 * k, IDESC_BF16, k > 0);
            #pragma unroll
            for (int k = 0; k < 4; ++k)
                mma_f16_ss(acc, dAH + 2 * k, dBL + 2 * k, IDESC_BF16, 1);
            #pragma unroll
            for (int k = 0; k < 4; ++k)
                mma_f16_ss(acc, dAL + 2 * k, dBH + 2 * k, IDESC_BF16, 1);
            asm volatile(
                "tcgen05.commit.cta_group::1.mbarrier::arrive::one.shared::cluster.b64 [%0];"
                :: "r"(pb ? mbar1 : mbar0) : "memory");
        }
    };

    // drain buffer pb: wait MMA, LDTM, bias-add, store row tokC
    auto drain = [&](int pb, int tokC, int MtC) {
        mbar_wait(pb ? mbar1 : mbar0, pb ? ph1 : ph0);
        if (pb) ph1 ^= 1; else ph0 ^= 1;
        asm volatile("tcgen05.fence::after_thread_sync;" ::: "memory");
        uint32_t dr[32], dr2[32];
        LDTM_X32(dr,  tmem + pb * 64);
        LDTM_X32(dr2, tmem + pb * 64 + 32);
        asm volatile("tcgen05.wait::ld.sync.aligned;" ::: "memory");
        if (row < MtC) {
            float4* orow = (float4*)(out + (size_t)tokC * D);
            #pragma unroll
            for (int q = 0; q < 16; ++q) {
                const uint32_t* s = (q < 8) ? &dr[q * 4] : &dr2[(q - 8) * 4];
                float4 bb = *(const float4*)(sB + q * 4);
                float4 o;
                o.x = __uint_as_float(s[0]) + bb.x;
                o.y = __uint_as_float(s[1]) + bb.y;
                o.z = __uint_as_float(s[2]) + bb.z;
                o.w = __uint_as_float(s[3]) + bb.w;
                orow[q] = o;
            }
        }
        asm volatile("tcgen05.fence::before_thread_sync;" ::: "memory");
    };

    // ---- prologue: first ticket ----
    if (tid == 0) *sTick = atomicAdd(&g_ticket, 1);
    __syncthreads();
    int t = *sTick;

    if (t < totalTiles) {
        fetchTile(t);
        loadB(); eCur = e;
        stageA(0);
        asm volatile("fence.proxy.async.shared::cta;" ::: "memory");
        __syncthreads();
        issueMMA(0);

        int cur = 0;
        int tokC = tok, MtC = Mt;

        for (;;) {
            if (tid == 0) *sTick = atomicAdd(&g_ticket, 1);
            __syncthreads();
            const int tn = *sTick;
            const bool has = (tn < totalTiles);

            if (has) fetchTile(tn);          // gather LDGs in flight

            drain(cur, tokC, MtC);           // hides gather latency
            if (!has) break;

            if (e != eCur) { loadB(); eCur = e; }   // no MMA in flight here
            stageA(cur ^ 1);
            asm volatile("fence.proxy.async.shared::cta;" ::: "memory");
            __syncthreads();
            issueMMA(cur ^ 1);

            cur ^= 1;
            tokC = tok; MtC = Mt;
        }
    }

    __syncthreads();
    if (tid == 0) {
        asm volatile("mbarrier.inval.shared.b64 [%0];" :: "r"(mbar0) : "memory");
        asm volatile("mbarrier.inval.shared.b64 [%0];" :: "r"(mbar1) : "memory");
    }
    __syncthreads();
    if (wid == 0)
        asm volatile("tcgen05.dealloc.cta_group::1.sync.aligned.b32 %0, 128;"
                     :: "r"(tmem));

#else   // !TCGEN_OK — generic-PTX fallback (compiles everywhere; sm_103a cubin runs)
    __syncthreads();
    const int totalTiles = sMeta[8];
    for (;;) {
        if (tid == 0) *sTick = atomicAdd(&g_ticket, 1);
        __syncthreads();
        const int t = *sTick;
        if (t >= totalTiles) break;

        int e = 0;
        #pragma unroll
        for (int q = 1; q < EXPERTS; ++q) if (t >= sMeta[q]) e = q;
        const int ti = t - sMeta[e];
        const int rowStart = sMeta[9 + e] + ti * TILE;
        const int Mt = min(TILE, sMeta[17 + e] - ti * TILE);

        const int tok = g_perm[rowStart + (row < Mt ? row : 0)];
        const float* frow = features + (size_t)tok * D;
        float v[D];
        #pragma unroll
        for (int k = 0; k < D; ++k) v[k] = frow[k];

        if (row < Mt) {
            const float* We = W + (size_t)e * D * D;
            for (int j = 0; j < D; ++j) {
                float s = b[e * D + j];
                #pragma unroll 16
                for (int k = 0; k < D; ++k) s = fmaf(v[k], We[(size_t)k * D + j], s);
                out[(size_t)tok * D + j] = s;
            }
        }
        __syncthreads();
    }
#endif
}

// ---------------- launch ----------------
extern "C" void kernel_launch(void* const* d_in, const int* in_sizes, int n_in,
                              void* d_out, int out_size) {
    const float* features = (const float*)d_in[0];
    const int*   inds     = (const int*)d_in[1];
    const float* W        = (const float*)d_in[2];
    const float* b        = (const float*)d_in[3];
    float*       out      = (float*)d_out;

    int N = in_sizes[0] / D;

    (void)cudaFuncSetAttribute(gemm_kernel,
                               cudaFuncAttributeMaxDynamicSharedMemorySize,
                               SMEM_SZ);

    int nScan = (N + SCAN_TOKENS - 1) / SCAN_TOKENS;
    count_kernel<<<nScan, SCAN_TPB>>>(inds, N);
    scan_kernel<<<1, NUM_SCAN_CTAS>>>();
    scatter_kernel<<<nScan, SCAN_TPB>>>(inds, N);
    gemm_kernel<<<NCTA_GEMM, GBLOCK, SMEM_SZ>>>(features, W, b, out);
}